// round 15
// baseline (speedup 1.0000x reference)
#include <cuda_runtime.h>
#include <cuda_bf16.h>

#define NB 2
#define NV 5
#define NC 32
#define ND 48
#define NH 128
#define NW 160
#define NHW  (NH*NW)
#define NDHW (ND*NHW)
#define NBDHW (NB*NDHW)

// Scratch (static __device__ arrays: allocation-free per harness rules)
__device__ __align__(16) float g_featT[NB*NV*NH*NW*NC];   // (b,v,h,w,c)  ~26 MB
__device__ float g_S[27*NBDHW];                            // 27 reduced fields ~212 MB
__device__ float g_cost[NBDHW];                            // (b,d,h,w)
__device__ float g_proj[NB*NV*12];                         // rot(9)+trans(3) per (b,v)

// ---------------------------------------------------------------------------
// Kernel 0: projection matrices.  ref = combine(b,0); P = combine(b,v) @ inv(ref)
// ---------------------------------------------------------------------------
__device__ void combine_mat(const float* pm, int b, int v, float out[16]) {
    const float* E = pm + ((b*NV + v)*2 + 0)*16;
    const float* K = pm + ((b*NV + v)*2 + 1)*16;
    for (int i = 0; i < 3; i++)
        for (int j = 0; j < 4; j++) {
            float s = 0.f;
            for (int k = 0; k < 3; k++) s += K[i*4+k]*E[k*4+j];
            out[i*4+j] = s;
        }
    for (int j = 0; j < 4; j++) out[12+j] = E[12+j];
}

__device__ void inv4(const float A[16], float out[16]) {
    float M[4][8];
    for (int i = 0; i < 4; i++) {
        for (int j = 0; j < 4; j++) { M[i][j] = A[i*4+j]; M[i][4+j] = (i == j) ? 1.f : 0.f; }
    }
    for (int c = 0; c < 4; c++) {
        int p = c; float best = fabsf(M[c][c]);
        for (int r = c+1; r < 4; r++) { float a = fabsf(M[r][c]); if (a > best) { best = a; p = r; } }
        if (p != c) for (int j = 0; j < 8; j++) { float t = M[c][j]; M[c][j] = M[p][j]; M[p][j] = t; }
        float inv = 1.f / M[c][c];
        for (int j = 0; j < 8; j++) M[c][j] *= inv;
        for (int r = 0; r < 4; r++) {
            if (r == c) continue;
            float f = M[r][c];
            for (int j = 0; j < 8; j++) M[r][j] -= f*M[c][j];
        }
    }
    for (int i = 0; i < 4; i++)
        for (int j = 0; j < 4; j++) out[i*4+j] = M[i][4+j];
}

__global__ void proj_kernel(const float* __restrict__ pm) {
    int tid = threadIdx.x;
    if (tid >= NB*(NV-1)) return;
    int b = tid / (NV-1);
    int v = 1 + tid % (NV-1);
    float ref[16], refInv[16], src[16], P[16];
    combine_mat(pm, b, 0, ref);
    inv4(ref, refInv);
    combine_mat(pm, b, v, src);
    for (int i = 0; i < 4; i++)
        for (int j = 0; j < 4; j++) {
            float s = 0.f;
            for (int k = 0; k < 4; k++) s += src[i*4+k]*refInv[k*4+j];
            P[i*4+j] = s;
        }
    float* o = g_proj + (b*NV + v)*12;
    for (int i = 0; i < 3; i++)
        for (int j = 0; j < 3; j++) o[i*3+j] = P[i*4+j];
    o[9]  = P[3];
    o[10] = P[7];
    o[11] = P[11];
}

// ---------------------------------------------------------------------------
// Kernel 1: transpose features (b,v,c,h,w) -> (b,v,h,w,c)
// ---------------------------------------------------------------------------
__global__ void transpose_kernel(const float* __restrict__ feat) {
    __shared__ float tile[32][33];
    int bv = blockIdx.z;
    int h  = blockIdx.y;
    int w0 = blockIdx.x * 32;
    int tx = threadIdx.x, ty = threadIdx.y;
#pragma unroll
    for (int k = 0; k < 4; k++) {
        int c = ty + 8*k;
        tile[c][tx] = feat[(bv*NC + c)*NHW + h*NW + w0 + tx];
    }
    __syncthreads();
#pragma unroll
    for (int k = 0; k < 4; k++) {
        int wl = ty + 8*k;
        g_featT[((bv*NH + h)*NW + w0 + wl)*NC + tx] = tile[tx][wl];
    }
}

// ---------------------------------------------------------------------------
// Kernel 2: fused warp + variance + channel-reduction into 27 S fields.
// Block: 256 threads = 32 positions (consecutive w) x 8 channel-quad lanes.
// ---------------------------------------------------------------------------
__global__ void __launch_bounds__(256) fuse_kernel(const float* __restrict__ dv,
                                                   const float* __restrict__ wreg) {
    __shared__ float4 w4[27*8];
    __shared__ float  Sst[27*32];
    int tid = threadIdx.x;
    if (tid < 216) {
        int tau = tid >> 3, cq = tid & 7;
        w4[tid] = make_float4(wreg[(4*cq+0)*27 + tau], wreg[(4*cq+1)*27 + tau],
                              wreg[(4*cq+2)*27 + tau], wreg[(4*cq+3)*27 + tau]);
    }

    int bz = blockIdx.z;
    int b = bz / ND, d = bz % ND;
    int h  = blockIdx.y;
    int w0 = blockIdx.x * 32;
    int g  = tid >> 3, cq = tid & 7;
    int w  = w0 + g;
    float depth = dv[b*ND + d];
    float x = (float)w, y = (float)h;

    int   idx[4][4];
    float wt[4][4];
#pragma unroll
    for (int vi = 0; vi < 4; vi++) {
        const float* pr = g_proj + (b*NV + vi + 1)*12;
        float rx = pr[0]*x + pr[1]*y + pr[2];
        float ry = pr[3]*x + pr[4]*y + pr[5];
        float rz = pr[6]*x + pr[7]*y + pr[8];
        float px = fmaf(rx, depth, pr[9]);
        float py = fmaf(ry, depth, pr[10]);
        float pz = fmaf(rz, depth, pr[11]);
        float inv = 1.f / pz;
        float ix = px * inv, iy = py * inv;
        float x0 = floorf(ix), y0 = floorf(iy);
        float wx1 = ix - x0, wx0 = 1.f - wx1;
        float wy1 = iy - y0, wy0 = 1.f - wy1;
        float x1 = x0 + 1.f, y1 = y0 + 1.f;
        float vx0 = (x0 >= 0.f && x0 <= (float)(NW-1)) ? 1.f : 0.f;
        float vx1 = (x1 >= 0.f && x1 <= (float)(NW-1)) ? 1.f : 0.f;
        float vy0 = (y0 >= 0.f && y0 <= (float)(NH-1)) ? 1.f : 0.f;
        float vy1 = (y1 >= 0.f && y1 <= (float)(NH-1)) ? 1.f : 0.f;
        int xi0 = (int)fminf(fmaxf(x0, 0.f), (float)(NW-1));
        int xi1 = (int)fminf(fmaxf(x1, 0.f), (float)(NW-1));
        int yi0 = (int)fminf(fmaxf(y0, 0.f), (float)(NH-1));
        int yi1 = (int)fminf(fmaxf(y1, 0.f), (float)(NH-1));
        int base = (b*NV + vi + 1)*NH;
        idx[vi][0] = ((base + yi0)*NW + xi0)*8;
        idx[vi][1] = ((base + yi0)*NW + xi1)*8;
        idx[vi][2] = ((base + yi1)*NW + xi0)*8;
        idx[vi][3] = ((base + yi1)*NW + xi1)*8;
        wt[vi][0] = wx0*wy0*vx0*vy0;
        wt[vi][1] = wx1*wy0*vx1*vy0;
        wt[vi][2] = wx0*wy1*vx0*vy1;
        wt[vi][3] = wx1*wy1*vx1*vy1;
    }
    __syncthreads();  // w4 visible

    const float4* __restrict__ fT = (const float4*)g_featT;
    float4 rf = fT[((b*NV*NH + h)*NW + w)*8 + cq];
    float4 s = rf;
    float4 q = make_float4(rf.x*rf.x, rf.y*rf.y, rf.z*rf.z, rf.w*rf.w);
#pragma unroll
    for (int vi = 0; vi < 4; vi++) {
        float4 t0 = fT[idx[vi][0] + cq];
        float4 t1 = fT[idx[vi][1] + cq];
        float4 t2 = fT[idx[vi][2] + cq];
        float4 t3 = fT[idx[vi][3] + cq];
        float a0 = wt[vi][0], a1 = wt[vi][1], a2 = wt[vi][2], a3 = wt[vi][3];
        float vx = fmaf(a0, t0.x, fmaf(a1, t1.x, fmaf(a2, t2.x, a3*t3.x)));
        float vy = fmaf(a0, t0.y, fmaf(a1, t1.y, fmaf(a2, t2.y, a3*t3.y)));
        float vz = fmaf(a0, t0.z, fmaf(a1, t1.z, fmaf(a2, t2.z, a3*t3.z)));
        float vw = fmaf(a0, t0.w, fmaf(a1, t1.w, fmaf(a2, t2.w, a3*t3.w)));
        s.x += vx; q.x = fmaf(vx, vx, q.x);
        s.y += vy; q.y = fmaf(vy, vy, q.y);
        s.z += vz; q.z = fmaf(vz, vz, q.z);
        s.w += vw; q.w = fmaf(vw, vw, q.w);
    }
    const float invV = 1.f / (float)NV;
    float4 var;
    { float m = s.x*invV; var.x = fmaf(-m, m, q.x*invV); }
    { float m = s.y*invV; var.y = fmaf(-m, m, q.y*invV); }
    { float m = s.z*invV; var.z = fmaf(-m, m, q.z*invV); }
    { float m = s.w*invV; var.w = fmaf(-m, m, q.w*invV); }

    // 27 channel-dot-products, reduced across the 8-lane group.
#pragma unroll
    for (int tau = 0; tau < 27; tau++) {
        float4 wv = w4[tau*8 + cq];
        float p = wv.x*var.x + wv.y*var.y + wv.z*var.z + wv.w*var.w;
        p += __shfl_xor_sync(0xffffffffu, p, 1);
        p += __shfl_xor_sync(0xffffffffu, p, 2);
        p += __shfl_xor_sync(0xffffffffu, p, 4);
        if (cq == 0) Sst[tau*32 + g] = p;
    }
    __syncthreads();

    int posbase = ((b*ND + d)*NH + h)*NW + w0;
    for (int j = tid; j < 27*32; j += 256) {
        int tau = j >> 5, gg = j & 31;
        g_S[tau*NBDHW + posbase + gg] = Sst[j];
    }
}

// ---------------------------------------------------------------------------
// Kernel 3: cost(p) = sum_tau S_tau(p + tau - 1)   (zero-padded 3x3x3)
// ---------------------------------------------------------------------------
__global__ void conv_kernel() {
    int t = blockIdx.x*blockDim.x + threadIdx.x;
    if (t >= NBDHW) return;
    int w = t % NW; int tmp = t / NW;
    int h = tmp % NH; tmp /= NH;
    int d = tmp % ND; int b = tmp / ND;
    float acc = 0.f;
#pragma unroll
    for (int kd = 0; kd < 3; kd++) {
        int dd = d + kd - 1; if ((unsigned)dd >= ND) continue;
#pragma unroll
        for (int kh = 0; kh < 3; kh++) {
            int hh = h + kh - 1; if ((unsigned)hh >= NH) continue;
#pragma unroll
            for (int kw = 0; kw < 3; kw++) {
                int ww = w + kw - 1; if ((unsigned)ww >= NW) continue;
                int tau = (kd*3 + kh)*3 + kw;
                acc += g_S[tau*NBDHW + ((b*ND + dd)*NH + hh)*NW + ww];
            }
        }
    }
    g_cost[t] = acc;
}

// ---------------------------------------------------------------------------
// Kernel 4: softmax over D + itg + depth + conf.  One thread per (b,h,w).
// ---------------------------------------------------------------------------
__global__ void __launch_bounds__(256) softmax_kernel(const float* __restrict__ dv,
                                                      float* __restrict__ out) {
    int t = blockIdx.x*blockDim.x + threadIdx.x;
    if (t >= NB*NHW) return;
    int b = t / NHW; int rem = t % NHW;
    const float* cb = g_cost + b*NDHW + rem;

    float e[ND];
    float m = -1e30f;
#pragma unroll
    for (int d = 0; d < ND; d++) { e[d] = cb[d*NHW]; m = fmaxf(m, e[d]); }
    float se = 0.f;
#pragma unroll
    for (int d = 0; d < ND; d++) { e[d] = __expf(e[d] - m); se += e[d]; }
    float inv = 1.f / se;
    float sa = 0.f;
#pragma unroll
    for (int d = 0; d < ND; d++) { e[d] *= inv; sa += fabsf(e[d]); }  // e = prob
    float isa = 1.f / fmaxf(sa, 1e-12f);

    float depth = 0.f, dif = 0.f;
    const float* dvb = dv + b*ND;
    float* itg = out + 2*NB*NHW + b*NDHW + rem;
#pragma unroll
    for (int d = 0; d < ND; d++) {
        float it = e[d] * isa;
        itg[d*NHW] = it;
        depth = fmaf(it, dvb[d], depth);
        dif   = fmaf(e[d], (float)d, dif);
    }
    int di = (int)dif;
    di = min(max(di, 0), ND - 1);
    float conf = 0.f;
#pragma unroll
    for (int d = 0; d < ND; d++) {
        if (d >= di - 1 && d <= di + 2) conf += e[d];
    }
    out[t] = depth;
    out[NB*NHW + t] = conf;
}

// ---------------------------------------------------------------------------
extern "C" void kernel_launch(void* const* d_in, const int* in_sizes, int n_in,
                              void* d_out, int out_size) {
    const float* feat = (const float*)d_in[0];  // (B,V,C,H,W)
    const float* pm   = (const float*)d_in[1];  // (B,V,2,4,4)
    const float* dv   = (const float*)d_in[2];  // (B,D)
    const float* wreg = (const float*)d_in[3];  // (1,C,3,3,3)
    float* out = (float*)d_out;                 // depth | conf | itg

    proj_kernel<<<1, 32>>>(pm);
    transpose_kernel<<<dim3(NW/32, NH, NB*NV), dim3(32, 8)>>>(feat);
    fuse_kernel<<<dim3(NW/32, NH, NB*ND), 256>>>(dv, wreg);
    conv_kernel<<<(NBDHW + 255)/256, 256>>>();
    softmax_kernel<<<(NB*NHW + 255)/256, 256>>>(dv, out);
}

// round 16
// speedup vs baseline: 1.0294x; 1.0294x over previous
#include <cuda_runtime.h>
#include <cuda_bf16.h>

#define NB 2
#define NV 5
#define NC 32
#define ND 48
#define NH 128
#define NW 160
#define NHW  (NH*NW)
#define NDHW (ND*NHW)
#define NBDHW (NB*NDHW)

typedef unsigned long long u64;

// Scratch (static __device__ arrays: allocation-free per harness rules)
__device__ __align__(16) float g_featT[NB*NV*NH*NW*NC];   // (b,v,h,w,c)  ~26 MB
__device__ float g_S[27*NBDHW];                            // 27 reduced fields ~212 MB
__device__ float g_cost[NBDHW];                            // (b,d,h,w)
__device__ float g_proj[NB*NV*12];                         // rot(9)+trans(3) per (b,v)

// ---------------- f32x2 packed helpers (sm_100+) ----------------
__device__ __forceinline__ u64 f2pk(float lo, float hi) {
    u64 r; asm("mov.b64 %0,{%1,%2};" : "=l"(r) : "f"(lo), "f"(hi)); return r;
}
__device__ __forceinline__ void f2upk(u64 v, float& lo, float& hi) {
    asm("mov.b64 {%0,%1},%2;" : "=f"(lo), "=f"(hi) : "l"(v));
}
__device__ __forceinline__ u64 f2fma(u64 a, u64 b, u64 c) {
    u64 d; asm("fma.rn.f32x2 %0,%1,%2,%3;" : "=l"(d) : "l"(a), "l"(b), "l"(c)); return d;
}
__device__ __forceinline__ u64 f2mul(u64 a, u64 b) {
    u64 d; asm("mul.rn.f32x2 %0,%1,%2;" : "=l"(d) : "l"(a), "l"(b)); return d;
}
__device__ __forceinline__ u64 f2add(u64 a, u64 b) {
    u64 d; asm("add.rn.f32x2 %0,%1,%2;" : "=l"(d) : "l"(a), "l"(b)); return d;
}

// ---------------------------------------------------------------------------
// Kernel 0: projection matrices.  ref = combine(b,0); P = combine(b,v) @ inv(ref)
// ---------------------------------------------------------------------------
__device__ void combine_mat(const float* pm, int b, int v, float out[16]) {
    const float* E = pm + ((b*NV + v)*2 + 0)*16;
    const float* K = pm + ((b*NV + v)*2 + 1)*16;
    for (int i = 0; i < 3; i++)
        for (int j = 0; j < 4; j++) {
            float s = 0.f;
            for (int k = 0; k < 3; k++) s += K[i*4+k]*E[k*4+j];
            out[i*4+j] = s;
        }
    for (int j = 0; j < 4; j++) out[12+j] = E[12+j];
}

__device__ void inv4(const float A[16], float out[16]) {
    float M[4][8];
    for (int i = 0; i < 4; i++) {
        for (int j = 0; j < 4; j++) { M[i][j] = A[i*4+j]; M[i][4+j] = (i == j) ? 1.f : 0.f; }
    }
    for (int c = 0; c < 4; c++) {
        int p = c; float best = fabsf(M[c][c]);
        for (int r = c+1; r < 4; r++) { float a = fabsf(M[r][c]); if (a > best) { best = a; p = r; } }
        if (p != c) for (int j = 0; j < 8; j++) { float t = M[c][j]; M[c][j] = M[p][j]; M[p][j] = t; }
        float inv = 1.f / M[c][c];
        for (int j = 0; j < 8; j++) M[c][j] *= inv;
        for (int r = 0; r < 4; r++) {
            if (r == c) continue;
            float f = M[r][c];
            for (int j = 0; j < 8; j++) M[r][j] -= f*M[c][j];
        }
    }
    for (int i = 0; i < 4; i++)
        for (int j = 0; j < 4; j++) out[i*4+j] = M[i][4+j];
}

__global__ void proj_kernel(const float* __restrict__ pm) {
    int tid = threadIdx.x;
    if (tid >= NB*(NV-1)) return;
    int b = tid / (NV-1);
    int v = 1 + tid % (NV-1);
    float ref[16], refInv[16], src[16], P[16];
    combine_mat(pm, b, 0, ref);
    inv4(ref, refInv);
    combine_mat(pm, b, v, src);
    for (int i = 0; i < 4; i++)
        for (int j = 0; j < 4; j++) {
            float s = 0.f;
            for (int k = 0; k < 4; k++) s += src[i*4+k]*refInv[k*4+j];
            P[i*4+j] = s;
        }
    float* o = g_proj + (b*NV + v)*12;
    for (int i = 0; i < 3; i++)
        for (int j = 0; j < 3; j++) o[i*3+j] = P[i*4+j];
    o[9]  = P[3];
    o[10] = P[7];
    o[11] = P[11];
}

// ---------------------------------------------------------------------------
// Kernel 1: transpose features (b,v,c,h,w) -> (b,v,h,w,c)
// ---------------------------------------------------------------------------
__global__ void transpose_kernel(const float* __restrict__ feat) {
    __shared__ float tile[32][33];
    int bv = blockIdx.z;
    int h  = blockIdx.y;
    int w0 = blockIdx.x * 32;
    int tx = threadIdx.x, ty = threadIdx.y;
#pragma unroll
    for (int k = 0; k < 4; k++) {
        int c = ty + 8*k;
        tile[c][tx] = feat[(bv*NC + c)*NHW + h*NW + w0 + tx];
    }
    __syncthreads();
#pragma unroll
    for (int k = 0; k < 4; k++) {
        int wl = ty + 8*k;
        g_featT[((bv*NH + h)*NW + w0 + wl)*NC + tx] = tile[tx][wl];
    }
}

// ---------------------------------------------------------------------------
// Kernel 2: fused warp + variance + channel-reduction into 27 S fields.
// Block: 256 threads = 32 positions (consecutive w) x 8 channel-quad lanes.
//   Phase A (warp 0 only): per-position projection -> 4 tap indices + packed weights
//   Phase B (all): bilinear gather + variance in f32x2
//   Phase C (all): shuffle-free 27-tau dot products, each lane owns 4 taus
// ---------------------------------------------------------------------------
__global__ void __launch_bounds__(256) fuse_kernel(const float* __restrict__ dv,
                                                   const float* __restrict__ wreg) {
    __shared__ float Wsm[27*36];      // W[tau][c], row stride 36 (bank-conflict free)
    __shared__ int4  sIdx[32*5];      // [g][vi] at g*5+vi
    __shared__ u64   sWt[32*18];      // [g][vi*4+k] at g*18+vi*4+k (packed pairs)
    __shared__ float varS[32*36];     // var[g][c], row stride 36
    __shared__ float Sst[27*33];      // S[tau][g], row stride 33

    int tid = threadIdx.x;
    for (int j = tid; j < 27*32; j += 256) {
        int tau = j >> 5, c = j & 31;
        Wsm[tau*36 + c] = wreg[c*27 + tau];
    }

    int bz = blockIdx.z;
    int b = bz / ND, d = bz % ND;
    int h  = blockIdx.y;
    int w0 = blockIdx.x * 32;
    int g  = tid >> 3, cq = tid & 7;

    // ---- Phase A: address math, one thread per position (warp 0) ----
    if (tid < 32) {
        int gp = tid;
        float depth = dv[b*ND + d];
        float x = (float)(w0 + gp), y = (float)h;
#pragma unroll
        for (int vi = 0; vi < 4; vi++) {
            const float* pr = g_proj + (b*NV + vi + 1)*12;
            float rx = pr[0]*x + pr[1]*y + pr[2];
            float ry = pr[3]*x + pr[4]*y + pr[5];
            float rz = pr[6]*x + pr[7]*y + pr[8];
            float px = fmaf(rx, depth, pr[9]);
            float py = fmaf(ry, depth, pr[10]);
            float pz = fmaf(rz, depth, pr[11]);
            float inv = 1.f / pz;
            float ix = px * inv, iy = py * inv;
            float x0 = floorf(ix), y0 = floorf(iy);
            float wx1 = ix - x0, wx0 = 1.f - wx1;
            float wy1 = iy - y0, wy0 = 1.f - wy1;
            float x1 = x0 + 1.f, y1 = y0 + 1.f;
            float vx0 = (x0 >= 0.f && x0 <= (float)(NW-1)) ? 1.f : 0.f;
            float vx1 = (x1 >= 0.f && x1 <= (float)(NW-1)) ? 1.f : 0.f;
            float vy0 = (y0 >= 0.f && y0 <= (float)(NH-1)) ? 1.f : 0.f;
            float vy1 = (y1 >= 0.f && y1 <= (float)(NH-1)) ? 1.f : 0.f;
            int xi0 = (int)fminf(fmaxf(x0, 0.f), (float)(NW-1));
            int xi1 = (int)fminf(fmaxf(x1, 0.f), (float)(NW-1));
            int yi0 = (int)fminf(fmaxf(y0, 0.f), (float)(NH-1));
            int yi1 = (int)fminf(fmaxf(y1, 0.f), (float)(NH-1));
            int base = (b*NV + vi + 1)*NH;
            int4 id;
            id.x = ((base + yi0)*NW + xi0)*8;
            id.y = ((base + yi0)*NW + xi1)*8;
            id.z = ((base + yi1)*NW + xi0)*8;
            id.w = ((base + yi1)*NW + xi1)*8;
            sIdx[gp*5 + vi] = id;
            float a0 = wx0*wy0*vx0*vy0;
            float a1 = wx1*wy0*vx1*vy0;
            float a2 = wx0*wy1*vx0*vy1;
            float a3 = wx1*wy1*vx1*vy1;
            sWt[gp*18 + vi*4 + 0] = f2pk(a0, a0);
            sWt[gp*18 + vi*4 + 1] = f2pk(a1, a1);
            sWt[gp*18 + vi*4 + 2] = f2pk(a2, a2);
            sWt[gp*18 + vi*4 + 3] = f2pk(a3, a3);
        }
    }
    __syncthreads();

    // ---- Phase B: bilinear gather + variance (f32x2, 4 channels per thread) ----
    const ulonglong2* __restrict__ fT = (const ulonglong2*)g_featT;
    ulonglong2 rf = fT[((b*NV*NH + h)*NW + (w0 + g))*8 + cq];
    u64 sA = rf.x, sB = rf.y;
    u64 qA = f2mul(rf.x, rf.x), qB = f2mul(rf.y, rf.y);
#pragma unroll
    for (int vi = 0; vi < 4; vi++) {
        int4 id = sIdx[g*5 + vi];
        ulonglong2 w01 = *(const ulonglong2*)&sWt[g*18 + vi*4];
        ulonglong2 w23 = *(const ulonglong2*)&sWt[g*18 + vi*4 + 2];
        ulonglong2 t0 = fT[id.x + cq];
        ulonglong2 t1 = fT[id.y + cq];
        ulonglong2 t2 = fT[id.z + cq];
        ulonglong2 t3 = fT[id.w + cq];
        u64 vA = f2fma(w01.x, t0.x, f2fma(w01.y, t1.x, f2fma(w23.x, t2.x, f2mul(w23.y, t3.x))));
        u64 vB = f2fma(w01.x, t0.y, f2fma(w01.y, t1.y, f2fma(w23.x, t2.y, f2mul(w23.y, t3.y))));
        sA = f2add(sA, vA); sB = f2add(sB, vB);
        qA = f2fma(vA, vA, qA); qB = f2fma(vB, vB, qB);
    }
    const float invV = 1.f / (float)NV;
    {
        float s0,s1,s2,s3,q0,q1,q2,q3, m;
        f2upk(sA, s0, s1); f2upk(sB, s2, s3);
        f2upk(qA, q0, q1); f2upk(qB, q2, q3);
        float4 var;
        m = s0*invV; var.x = fmaf(-m, m, q0*invV);
        m = s1*invV; var.y = fmaf(-m, m, q1*invV);
        m = s2*invV; var.z = fmaf(-m, m, q2*invV);
        m = s3*invV; var.w = fmaf(-m, m, q3*invV);
        *(float4*)&varS[g*36 + cq*4] = var;
    }
    __syncthreads();

    // ---- Phase C: each lane computes 4 complete taus (no shuffles) ----
    ulonglong2 va[8];
#pragma unroll
    for (int i = 0; i < 8; i++) va[i] = *(const ulonglong2*)&varS[g*36 + i*4];
#pragma unroll
    for (int j = 0; j < 4; j++) {
        int tau = cq + 8*j;
        if (tau < 27) {
            const ulonglong2* wr = (const ulonglong2*)&Wsm[tau*36];
            u64 acc = f2mul(wr[0].x, va[0].x);
            acc = f2fma(wr[0].y, va[0].y, acc);
#pragma unroll
            for (int i = 1; i < 8; i++) {
                ulonglong2 wv = wr[i];
                acc = f2fma(wv.x, va[i].x, acc);
                acc = f2fma(wv.y, va[i].y, acc);
            }
            float lo, hi; f2upk(acc, lo, hi);
            Sst[tau*33 + g] = lo + hi;
        }
    }
    __syncthreads();

    int posbase = ((b*ND + d)*NH + h)*NW + w0;
    for (int j = tid; j < 27*32; j += 256) {
        int tau = j >> 5, gg = j & 31;
        g_S[tau*NBDHW + posbase + gg] = Sst[tau*33 + gg];
    }
}

// ---------------------------------------------------------------------------
// Kernel 3: cost(p) = sum_tau S_tau(p + tau - 1)   (zero-padded 3x3x3)
// ---------------------------------------------------------------------------
__global__ void conv_kernel() {
    int t = blockIdx.x*blockDim.x + threadIdx.x;
    if (t >= NBDHW) return;
    int w = t % NW; int tmp = t / NW;
    int h = tmp % NH; tmp /= NH;
    int d = tmp % ND; int b = tmp / ND;
    float acc = 0.f;
    if (d >= 1 && d < ND-1 && h >= 1 && h < NH-1 && w >= 1 && w < NW-1) {
#pragma unroll
        for (int kd = 0; kd < 3; kd++)
#pragma unroll
            for (int kh = 0; kh < 3; kh++)
#pragma unroll
                for (int kw = 0; kw < 3; kw++) {
                    int tau = (kd*3 + kh)*3 + kw;
                    acc += g_S[tau*NBDHW + ((b*ND + d+kd-1)*NH + (h+kh-1))*NW + (w+kw-1)];
                }
    } else {
#pragma unroll
        for (int kd = 0; kd < 3; kd++) {
            int dd = d + kd - 1; if ((unsigned)dd >= ND) continue;
#pragma unroll
            for (int kh = 0; kh < 3; kh++) {
                int hh = h + kh - 1; if ((unsigned)hh >= NH) continue;
#pragma unroll
                for (int kw = 0; kw < 3; kw++) {
                    int ww = w + kw - 1; if ((unsigned)ww >= NW) continue;
                    int tau = (kd*3 + kh)*3 + kw;
                    acc += g_S[tau*NBDHW + ((b*ND + dd)*NH + hh)*NW + ww];
                }
            }
        }
    }
    g_cost[t] = acc;
}

// ---------------------------------------------------------------------------
// Kernel 4: softmax over D + itg + depth + conf.  One thread per (b,h,w).
// ---------------------------------------------------------------------------
__global__ void __launch_bounds__(256) softmax_kernel(const float* __restrict__ dv,
                                                      float* __restrict__ out) {
    int t = blockIdx.x*blockDim.x + threadIdx.x;
    if (t >= NB*NHW) return;
    int b = t / NHW; int rem = t % NHW;
    const float* cb = g_cost + b*NDHW + rem;

    float e[ND];
    float m = -1e30f;
#pragma unroll
    for (int d = 0; d < ND; d++) { e[d] = cb[d*NHW]; m = fmaxf(m, e[d]); }
    float se = 0.f;
#pragma unroll
    for (int d = 0; d < ND; d++) { e[d] = __expf(e[d] - m); se += e[d]; }
    float inv = 1.f / se;
    float sa = 0.f;
#pragma unroll
    for (int d = 0; d < ND; d++) { e[d] *= inv; sa += fabsf(e[d]); }  // e = prob
    float isa = 1.f / fmaxf(sa, 1e-12f);

    float depth = 0.f, dif = 0.f;
    const float* dvb = dv + b*ND;
    float* itg = out + 2*NB*NHW + b*NDHW + rem;
#pragma unroll
    for (int d = 0; d < ND; d++) {
        float it = e[d] * isa;
        itg[d*NHW] = it;
        depth = fmaf(it, dvb[d], depth);
        dif   = fmaf(e[d], (float)d, dif);
    }
    int di = (int)dif;
    di = min(max(di, 0), ND - 1);
    float conf = 0.f;
#pragma unroll
    for (int d = 0; d < ND; d++) {
        if (d >= di - 1 && d <= di + 2) conf += e[d];
    }
    out[t] = depth;
    out[NB*NHW + t] = conf;
}

// ---------------------------------------------------------------------------
extern "C" void kernel_launch(void* const* d_in, const int* in_sizes, int n_in,
                              void* d_out, int out_size) {
    const float* feat = (const float*)d_in[0];  // (B,V,C,H,W)
    const float* pm   = (const float*)d_in[1];  // (B,V,2,4,4)
    const float* dv   = (const float*)d_in[2];  // (B,D)
    const float* wreg = (const float*)d_in[3];  // (1,C,3,3,3)
    float* out = (float*)d_out;                 // depth | conf | itg

    proj_kernel<<<1, 32>>>(pm);
    transpose_kernel<<<dim3(NW/32, NH, NB*NV), dim3(32, 8)>>>(feat);
    fuse_kernel<<<dim3(NW/32, NH, NB*ND), 256>>>(dv, wreg);
    conv_kernel<<<(NBDHW + 255)/256, 256>>>();
    softmax_kernel<<<(NB*NHW + 255)/256, 256>>>(dv, out);
}

// round 17
// speedup vs baseline: 1.1444x; 1.1117x over previous
#include <cuda_runtime.h>
#include <cuda_bf16.h>

#define NB 2
#define NV 5
#define NC 32
#define ND 48
#define NH 128
#define NW 160
#define NHW  (NH*NW)
#define NDHW (ND*NHW)
#define NBDHW (NB*NDHW)

typedef unsigned long long u64;

// Scratch (static __device__ arrays: allocation-free per harness rules)
__device__ __align__(16) float g_featT[NB*NV*NH*NW*NC];   // (b,v,h,w,c)  ~26 MB
__device__ float g_S[9*NBDHW];                             // 9 d-folded fields ~70 MB
__device__ float g_cost[NBDHW];                            // (b,d,h,w)
__device__ float g_proj[NB*NV*12];                         // rot(9)+trans(3) per (b,v)

// ---------------- f32x2 packed helpers (sm_100+) ----------------
__device__ __forceinline__ u64 f2pk(float lo, float hi) {
    u64 r; asm("mov.b64 %0,{%1,%2};" : "=l"(r) : "f"(lo), "f"(hi)); return r;
}
__device__ __forceinline__ void f2upk(u64 v, float& lo, float& hi) {
    asm("mov.b64 {%0,%1},%2;" : "=f"(lo), "=f"(hi) : "l"(v));
}
__device__ __forceinline__ u64 f2fma(u64 a, u64 b, u64 c) {
    u64 d; asm("fma.rn.f32x2 %0,%1,%2,%3;" : "=l"(d) : "l"(a), "l"(b), "l"(c)); return d;
}
__device__ __forceinline__ u64 f2mul(u64 a, u64 b) {
    u64 d; asm("mul.rn.f32x2 %0,%1,%2;" : "=l"(d) : "l"(a), "l"(b)); return d;
}
__device__ __forceinline__ u64 f2add(u64 a, u64 b) {
    u64 d; asm("add.rn.f32x2 %0,%1,%2;" : "=l"(d) : "l"(a), "l"(b)); return d;
}

// ---------------------------------------------------------------------------
// Kernel 0: projection matrices.
// ---------------------------------------------------------------------------
__device__ void combine_mat(const float* pm, int b, int v, float out[16]) {
    const float* E = pm + ((b*NV + v)*2 + 0)*16;
    const float* K = pm + ((b*NV + v)*2 + 1)*16;
    for (int i = 0; i < 3; i++)
        for (int j = 0; j < 4; j++) {
            float s = 0.f;
            for (int k = 0; k < 3; k++) s += K[i*4+k]*E[k*4+j];
            out[i*4+j] = s;
        }
    for (int j = 0; j < 4; j++) out[12+j] = E[12+j];
}

__device__ void inv4(const float A[16], float out[16]) {
    float M[4][8];
    for (int i = 0; i < 4; i++) {
        for (int j = 0; j < 4; j++) { M[i][j] = A[i*4+j]; M[i][4+j] = (i == j) ? 1.f : 0.f; }
    }
    for (int c = 0; c < 4; c++) {
        int p = c; float best = fabsf(M[c][c]);
        for (int r = c+1; r < 4; r++) { float a = fabsf(M[r][c]); if (a > best) { best = a; p = r; } }
        if (p != c) for (int j = 0; j < 8; j++) { float t = M[c][j]; M[c][j] = M[p][j]; M[p][j] = t; }
        float inv = 1.f / M[c][c];
        for (int j = 0; j < 8; j++) M[c][j] *= inv;
        for (int r = 0; r < 4; r++) {
            if (r == c) continue;
            float f = M[r][c];
            for (int j = 0; j < 8; j++) M[r][j] -= f*M[c][j];
        }
    }
    for (int i = 0; i < 4; i++)
        for (int j = 0; j < 4; j++) out[i*4+j] = M[i][4+j];
}

__global__ void proj_kernel(const float* __restrict__ pm) {
    int tid = threadIdx.x;
    if (tid >= NB*(NV-1)) return;
    int b = tid / (NV-1);
    int v = 1 + tid % (NV-1);
    float ref[16], refInv[16], src[16], P[16];
    combine_mat(pm, b, 0, ref);
    inv4(ref, refInv);
    combine_mat(pm, b, v, src);
    for (int i = 0; i < 4; i++)
        for (int j = 0; j < 4; j++) {
            float s = 0.f;
            for (int k = 0; k < 4; k++) s += src[i*4+k]*refInv[k*4+j];
            P[i*4+j] = s;
        }
    float* o = g_proj + (b*NV + v)*12;
    for (int i = 0; i < 3; i++)
        for (int j = 0; j < 3; j++) o[i*3+j] = P[i*4+j];
    o[9]  = P[3];
    o[10] = P[7];
    o[11] = P[11];
}

// ---------------------------------------------------------------------------
// Kernel 1: transpose features (b,v,c,h,w) -> (b,v,h,w,c)
// ---------------------------------------------------------------------------
__global__ void transpose_kernel(const float* __restrict__ feat) {
    __shared__ float tile[32][33];
    int bv = blockIdx.z;
    int h  = blockIdx.y;
    int w0 = blockIdx.x * 32;
    int tx = threadIdx.x, ty = threadIdx.y;
#pragma unroll
    for (int k = 0; k < 4; k++) {
        int c = ty + 8*k;
        tile[c][tx] = feat[(bv*NC + c)*NHW + h*NW + w0 + tx];
    }
    __syncthreads();
#pragma unroll
    for (int k = 0; k < 4; k++) {
        int wl = ty + 8*k;
        g_featT[((bv*NH + h)*NW + w0 + wl)*NC + tx] = tile[tx][wl];
    }
}

// ---------------------------------------------------------------------------
// Kernel 2: fused warp + variance + channel-reduction + d-direction conv.
// Grid: (NW/32, NH, NB).  Block: 256 threads = 32 positions x 8 channel-quads.
// Each block loops over all ND depths -> tap lines stay L1-resident.
// Accumulates 9 (kh,kw) fields (already summed over kd) in smem, writes once.
// ---------------------------------------------------------------------------
// dynamic smem layout (bytes):
#define OFF_SIDX   0                                   // int4 [32*4]           2048
#define OFF_SWT    (OFF_SIDX + 32*4*16)                // u64  [32*18]          4608
#define OFF_S9     (OFF_SWT + 32*18*8)                 // f32  [9*48*33]        57024
#define OFF_WSM    (OFF_S9 + 9*48*33*4)                // f32  [27*36]          3888
#define OFF_VARS   (OFF_WSM + 27*36*4)                 // f32  [32*36]          4608
#define OFF_RAY    (OFF_VARS + 32*36*4)                // f32  [32*12]          1536
#define OFF_TRANS  (OFF_RAY + 32*12*4)                 // f32  [12]             48
#define OFF_DEPTH  (OFF_TRANS + 16*4)                  // f32  [48]             192
#define SMEM_TOTAL_FUSE (OFF_DEPTH + 48*4)

__global__ void __launch_bounds__(256) fuse_kernel(const float* __restrict__ dv,
                                                   const float* __restrict__ wreg) {
    extern __shared__ __align__(16) char dynsm[];
    int4*  sIdx  = (int4*)(dynsm + OFF_SIDX);     // [g*4 + vi]
    u64*   sWt   = (u64*) (dynsm + OFF_SWT);      // [g*18 + vi*4 + k]
    float* S9sm  = (float*)(dynsm + OFF_S9);      // [(khw*48 + dq)*33 + g]
    float* Wsm   = (float*)(dynsm + OFF_WSM);     // [tau*36 + c]
    float* varS  = (float*)(dynsm + OFF_VARS);    // [g*36 + c]
    float* sRay  = (float*)(dynsm + OFF_RAY);     // [g*12 + vi*3 + k]
    float* sTr   = (float*)(dynsm + OFF_TRANS);   // [vi*3 + k]
    float* sDep  = (float*)(dynsm + OFF_DEPTH);   // [d]

    int tid = threadIdx.x;
    int b  = blockIdx.z;
    int h  = blockIdx.y;
    int w0 = blockIdx.x * 32;
    int g  = tid >> 3, cq = tid & 7;

    for (int j = tid; j < 27*32; j += 256) {
        int tau = j >> 5, c = j & 31;
        Wsm[tau*36 + c] = wreg[c*27 + tau];
    }
    for (int j = tid; j < 9*48*33; j += 256) S9sm[j] = 0.f;
    if (tid < 48) sDep[tid] = dv[b*ND + tid];
    if (tid < 12) sTr[tid] = g_proj[(b*NV + 1 + tid/3)*12 + 9 + tid%3];
    if (tid < 128) {
        int gp = tid >> 2, vi = tid & 3;
        const float* pr = g_proj + (b*NV + vi + 1)*12;
        float x = (float)(w0 + gp), y = (float)h;
        sRay[gp*12 + vi*3 + 0] = pr[0]*x + pr[1]*y + pr[2];
        sRay[gp*12 + vi*3 + 1] = pr[3]*x + pr[4]*y + pr[5];
        sRay[gp*12 + vi*3 + 2] = pr[6]*x + pr[7]*y + pr[8];
    }
    __syncthreads();

    // Hoisted ref-pixel contribution (d-independent)
    const ulonglong2* __restrict__ fT = (const ulonglong2*)g_featT;
    ulonglong2 rf = fT[((b*NV*NH + h)*NW + (w0 + g))*8 + cq];
    u64 rqA = f2mul(rf.x, rf.x), rqB = f2mul(rf.y, rf.y);
    const float invV = 1.f / (float)NV;

    for (int dd = 0; dd < ND; dd++) {
        // ---- Phase A: per-position bilinear setup (warp 0) ----
        if (tid < 32) {
            int gp = tid;
            float depth = sDep[dd];
#pragma unroll
            for (int vi = 0; vi < 4; vi++) {
                float rx = sRay[gp*12 + vi*3 + 0];
                float ry = sRay[gp*12 + vi*3 + 1];
                float rz = sRay[gp*12 + vi*3 + 2];
                float px = fmaf(rx, depth, sTr[vi*3 + 0]);
                float py = fmaf(ry, depth, sTr[vi*3 + 1]);
                float pz = fmaf(rz, depth, sTr[vi*3 + 2]);
                float inv = 1.f / pz;
                float ix = px * inv, iy = py * inv;
                float x0 = floorf(ix), y0 = floorf(iy);
                float wx1 = ix - x0, wx0 = 1.f - wx1;
                float wy1 = iy - y0, wy0 = 1.f - wy1;
                float x1 = x0 + 1.f, y1 = y0 + 1.f;
                float vx0 = (x0 >= 0.f && x0 <= (float)(NW-1)) ? 1.f : 0.f;
                float vx1 = (x1 >= 0.f && x1 <= (float)(NW-1)) ? 1.f : 0.f;
                float vy0 = (y0 >= 0.f && y0 <= (float)(NH-1)) ? 1.f : 0.f;
                float vy1 = (y1 >= 0.f && y1 <= (float)(NH-1)) ? 1.f : 0.f;
                int xi0 = (int)fminf(fmaxf(x0, 0.f), (float)(NW-1));
                int xi1 = (int)fminf(fmaxf(x1, 0.f), (float)(NW-1));
                int yi0 = (int)fminf(fmaxf(y0, 0.f), (float)(NH-1));
                int yi1 = (int)fminf(fmaxf(y1, 0.f), (float)(NH-1));
                int base = (b*NV + vi + 1)*NH;
                int4 id;
                id.x = ((base + yi0)*NW + xi0)*8;
                id.y = ((base + yi0)*NW + xi1)*8;
                id.z = ((base + yi1)*NW + xi0)*8;
                id.w = ((base + yi1)*NW + xi1)*8;
                sIdx[gp*4 + vi] = id;
                float a0 = wx0*wy0*vx0*vy0;
                float a1 = wx1*wy0*vx1*vy0;
                float a2 = wx0*wy1*vx0*vy1;
                float a3 = wx1*wy1*vx1*vy1;
                sWt[gp*18 + vi*4 + 0] = f2pk(a0, a0);
                sWt[gp*18 + vi*4 + 1] = f2pk(a1, a1);
                sWt[gp*18 + vi*4 + 2] = f2pk(a2, a2);
                sWt[gp*18 + vi*4 + 3] = f2pk(a3, a3);
            }
        }
        __syncthreads();

        // ---- Phase B: bilinear gather + variance (f32x2, 4 ch/thread) ----
        u64 sA = rf.x, sB = rf.y;
        u64 qA = rqA, qB = rqB;
#pragma unroll
        for (int vi = 0; vi < 4; vi++) {
            int4 id = sIdx[g*4 + vi];
            ulonglong2 w01 = *(const ulonglong2*)&sWt[g*18 + vi*4];
            ulonglong2 w23 = *(const ulonglong2*)&sWt[g*18 + vi*4 + 2];
            ulonglong2 t0 = fT[id.x + cq];
            ulonglong2 t1 = fT[id.y + cq];
            ulonglong2 t2 = fT[id.z + cq];
            ulonglong2 t3 = fT[id.w + cq];
            u64 vA = f2fma(w01.x, t0.x, f2fma(w01.y, t1.x, f2fma(w23.x, t2.x, f2mul(w23.y, t3.x))));
            u64 vB = f2fma(w01.x, t0.y, f2fma(w01.y, t1.y, f2fma(w23.x, t2.y, f2mul(w23.y, t3.y))));
            sA = f2add(sA, vA); sB = f2add(sB, vB);
            qA = f2fma(vA, vA, qA); qB = f2fma(vB, vB, qB);
        }
        {
            float s0,s1,s2,s3,q0,q1,q2,q3, m;
            f2upk(sA, s0, s1); f2upk(sB, s2, s3);
            f2upk(qA, q0, q1); f2upk(qB, q2, q3);
            float4 var;
            m = s0*invV; var.x = fmaf(-m, m, q0*invV);
            m = s1*invV; var.y = fmaf(-m, m, q1*invV);
            m = s2*invV; var.z = fmaf(-m, m, q2*invV);
            m = s3*invV; var.w = fmaf(-m, m, q3*invV);
            *(float4*)&varS[g*36 + cq*4] = var;
        }
        __syncthreads();

        // ---- Phase C: 27-tau dots, accumulate into d-folded 9 fields ----
        ulonglong2 va[8];
#pragma unroll
        for (int i = 0; i < 8; i++) va[i] = *(const ulonglong2*)&varS[g*36 + i*4];
#pragma unroll
        for (int j = 0; j < 4; j++) {
            int tau = cq + 8*j;
            if (tau < 27) {
                const ulonglong2* wr = (const ulonglong2*)&Wsm[tau*36];
                u64 acc = f2mul(wr[0].x, va[0].x);
                acc = f2fma(wr[0].y, va[0].y, acc);
#pragma unroll
                for (int i = 1; i < 8; i++) {
                    ulonglong2 wv = wr[i];
                    acc = f2fma(wv.x, va[i].x, acc);
                    acc = f2fma(wv.y, va[i].y, acc);
                }
                float lo, hi; f2upk(acc, lo, hi);
                float p = lo + hi;
                int kd  = tau / 9;
                int khw = tau - kd*9;
                int dq  = dd + 1 - kd;
                if ((unsigned)dq < (unsigned)ND)
                    S9sm[(khw*48 + dq)*33 + g] += p;
            }
        }
        __syncthreads();
    }

    // ---- write 9 folded fields ----
    for (int j = tid; j < 9*48*32; j += 256) {
        int khw = j / (48*32);
        int r = j - khw*(48*32);
        int dq = r >> 5, gg = r & 31;
        g_S[khw*NBDHW + ((b*ND + dq)*NH + h)*NW + w0 + gg] = S9sm[(khw*48 + dq)*33 + gg];
    }
}

// ---------------------------------------------------------------------------
// Kernel 3: cost(p) = sum_{kh,kw} S9_{kh,kw}(d, h+kh-1, w+kw-1)
// ---------------------------------------------------------------------------
__global__ void conv_kernel() {
    int t = blockIdx.x*blockDim.x + threadIdx.x;
    if (t >= NBDHW) return;
    int w = t % NW; int tmp = t / NW;
    int h = tmp % NH;
    float acc = 0.f;
    if (h >= 1 && h < NH-1 && w >= 1 && w < NW-1) {
#pragma unroll
        for (int kh = 0; kh < 3; kh++)
#pragma unroll
            for (int kw = 0; kw < 3; kw++)
                acc += g_S[(kh*3 + kw)*NBDHW + t + (kh-1)*NW + (kw-1)];
    } else {
#pragma unroll
        for (int kh = 0; kh < 3; kh++) {
            int hh = h + kh - 1; if ((unsigned)hh >= NH) continue;
#pragma unroll
            for (int kw = 0; kw < 3; kw++) {
                int ww = w + kw - 1; if ((unsigned)ww >= NW) continue;
                acc += g_S[(kh*3 + kw)*NBDHW + t + (kh-1)*NW + (kw-1)];
            }
        }
    }
    g_cost[t] = acc;
}

// ---------------------------------------------------------------------------
// Kernel 4: softmax over D + itg + depth + conf.  One thread per (b,h,w).
// ---------------------------------------------------------------------------
__global__ void __launch_bounds__(256) softmax_kernel(const float* __restrict__ dv,
                                                      float* __restrict__ out) {
    int t = blockIdx.x*blockDim.x + threadIdx.x;
    if (t >= NB*NHW) return;
    int b = t / NHW; int rem = t % NHW;
    const float* cb = g_cost + b*NDHW + rem;

    float e[ND];
    float m = -1e30f;
#pragma unroll
    for (int d = 0; d < ND; d++) { e[d] = cb[d*NHW]; m = fmaxf(m, e[d]); }
    float se = 0.f;
#pragma unroll
    for (int d = 0; d < ND; d++) { e[d] = __expf(e[d] - m); se += e[d]; }
    float inv = 1.f / se;
    float sa = 0.f;
#pragma unroll
    for (int d = 0; d < ND; d++) { e[d] *= inv; sa += fabsf(e[d]); }  // e = prob
    float isa = 1.f / fmaxf(sa, 1e-12f);

    float depth = 0.f, dif = 0.f;
    const float* dvb = dv + b*ND;
    float* itg = out + 2*NB*NHW + b*NDHW + rem;
#pragma unroll
    for (int d = 0; d < ND; d++) {
        float it = e[d] * isa;
        itg[d*NHW] = it;
        depth = fmaf(it, dvb[d], depth);
        dif   = fmaf(e[d], (float)d, dif);
    }
    int di = (int)dif;
    di = min(max(di, 0), ND - 1);
    float conf = 0.f;
#pragma unroll
    for (int d = 0; d < ND; d++) {
        if (d >= di - 1 && d <= di + 2) conf += e[d];
    }
    out[t] = depth;
    out[NB*NHW + t] = conf;
}

// ---------------------------------------------------------------------------
extern "C" void kernel_launch(void* const* d_in, const int* in_sizes, int n_in,
                              void* d_out, int out_size) {
    const float* feat = (const float*)d_in[0];  // (B,V,C,H,W)
    const float* pm   = (const float*)d_in[1];  // (B,V,2,4,4)
    const float* dv   = (const float*)d_in[2];  // (B,D)
    const float* wreg = (const float*)d_in[3];  // (1,C,3,3,3)
    float* out = (float*)d_out;                 // depth | conf | itg

    static int smem_set = 0;
    if (!smem_set) {
        cudaFuncSetAttribute(fuse_kernel, cudaFuncAttributeMaxDynamicSharedMemorySize,
                             SMEM_TOTAL_FUSE);
        smem_set = 1;
    }

    proj_kernel<<<1, 32>>>(pm);
    transpose_kernel<<<dim3(NW/32, NH, NB*NV), dim3(32, 8)>>>(feat);
    fuse_kernel<<<dim3(NW/32, NH, NB), 256, SMEM_TOTAL_FUSE>>>(dv, wreg);
    conv_kernel<<<(NBDHW + 255)/256, 256>>>();
    softmax_kernel<<<(NB*NHW + 255)/256, 256>>>(dv, out);
}